// round 15
// baseline (speedup 1.0000x reference)
#include <cuda_runtime.h>
#include <cuda_bf16.h>
#include <stdint.h>

#define C 1280
#define NIMG 8192          // B*K = 2048*4
#define NPAT 2048
#define PAIRS 6
#define PC 15728640u       // 12288 * 1280  (mask plane stride per dropout)

// ---- GEMM tiling: CTA 128x256, 8 warps (2 M x 4 N), warp 64x64 ----
#define TMt 128
#define TNt 256
#define KCH 32             // bf16 K elems per chunk = 64 B/row
#define NCHUNK 120         // 3 planes * (1280/32)
#define NSTAGE 4
#define STAGE_BYTES 24576  // A 8KB + B 16KB
#define DYN_SMEM (NSTAGE * STAGE_BYTES)
#define MASK_ITERS 96      // 96 * 163840 threads == PAIRS*NPAT*C elements
#define TOT_THREADS 163840u

// Scratch — 256B-aligned: cp.async needs 16B, vector stores need 8B.
__device__ __align__(256) float g_Y0[NIMG * C];
__device__ __align__(256) float g_Y1[NIMG * C];
__device__ __align__(256) __nv_bfloat16 g_Xhi[NIMG * C];
__device__ __align__(256) __nv_bfloat16 g_Xlo[NIMG * C];
__device__ __align__(256) __nv_bfloat16 g_Bhi[2 * C * C];  // 0..1279: tap0, 1280..2559: tap1
__device__ __align__(256) __nv_bfloat16 g_Blo[2 * C * C];
__device__ __align__(256) uint8_t g_n1[PAIRS * NPAT * C];  // keep-count per (pair, c)

// ---------------- helpers ----------------
__device__ __forceinline__ uint32_t smem_u32(const void* p) {
    uint32_t a;
    asm("{ .reg .u64 t; cvta.to.shared.u64 t, %1; cvt.u32.u64 %0, t; }" : "=r"(a) : "l"(p));
    return a;
}
// 64B rows, swizzle XORs (row/2)&7 into the 16B-unit bits -> conflict-free ldmatrix
__device__ __forceinline__ uint32_t swz(uint32_t o) { return o ^ (((o >> 7) & 7u) << 4); }

__device__ __forceinline__ void cp16(uint32_t dst, const void* src) {
    asm volatile("cp.async.cg.shared.global [%0], [%1], 16;" :: "r"(dst), "l"(src) : "memory");
}
#define CP_COMMIT() asm volatile("cp.async.commit_group;" ::: "memory")

__device__ __forceinline__ void ldm_x4(uint32_t* r, uint32_t addr) {
    asm volatile("ldmatrix.sync.aligned.m8n8.x4.shared.b16 {%0,%1,%2,%3}, [%4];"
                 : "=r"(r[0]), "=r"(r[1]), "=r"(r[2]), "=r"(r[3]) : "r"(addr));
}
__device__ __forceinline__ void mma_bf16(float* c, const uint32_t* a, uint32_t b0, uint32_t b1) {
    asm volatile(
        "mma.sync.aligned.m16n8k16.row.col.f32.bf16.bf16.f32 "
        "{%0,%1,%2,%3}, {%4,%5,%6,%7}, {%8,%9}, {%0,%1,%2,%3};"
        : "+f"(c[0]), "+f"(c[1]), "+f"(c[2]), "+f"(c[3])
        : "r"(a[0]), "r"(a[1]), "r"(a[2]), "r"(a[3]), "r"(b0), "r"(b1));
}

// ---------------- Threefry-2x32, JAX partitionable stream ----------------
__device__ __forceinline__ uint32_t rotl32(uint32_t x, int r) {
    return __funnelshift_l(x, x, r);
}
__device__ __forceinline__ int tf_n1(uint32_t base) {
    const uint32_t ks0 = 0u, ks1 = 42u, ks2 = 0x1BD11BF0u;
    uint32_t x0[5], x1[5];
#pragma unroll
    for (int d = 0; d < 5; d++) {
        x0[d] = ks0;
        x1[d] = base + (uint32_t)d * PC + ks1;
    }
#define TF_ROUND(r)                                           \
    {                                                         \
        _Pragma("unroll") for (int e = 0; e < 5; e++) {       \
            x0[e] += x1[e];                                   \
            x1[e] = rotl32(x1[e], (r));                       \
            x1[e] ^= x0[e];                                   \
        }                                                     \
    }
#define TF_INJ(a, b)                                          \
    {                                                         \
        _Pragma("unroll") for (int e = 0; e < 5; e++) {       \
            x0[e] += (a); x1[e] += (b);                       \
        }                                                     \
    }
    TF_ROUND(13) TF_ROUND(15) TF_ROUND(26) TF_ROUND(6)  TF_INJ(ks1, ks2 + 1u)
    TF_ROUND(17) TF_ROUND(29) TF_ROUND(16) TF_ROUND(24) TF_INJ(ks2, ks0 + 2u)
    TF_ROUND(13) TF_ROUND(15) TF_ROUND(26) TF_ROUND(6)  TF_INJ(ks0, ks1 + 3u)
    TF_ROUND(17) TF_ROUND(29) TF_ROUND(16) TF_ROUND(24) TF_INJ(ks1, ks2 + 4u)
    TF_ROUND(13) TF_ROUND(15) TF_ROUND(26) TF_ROUND(6)  TF_INJ(ks2, ks0 + 5u)
#undef TF_ROUND
#undef TF_INJ
    int msum = 0;
#pragma unroll
    for (int d = 0; d < 5; d++) msum += (int)((x0[d] ^ x1[d]) >> 31);
    return 5 - msum;
}

// ---------------- prep: split fp32 -> bf16 hi/lo (vectorized x4) ----------------
__device__ __forceinline__ uint32_t bf2(float a, float b) {
    __nv_bfloat162 t = __floats2bfloat162_rn(a, b);
    return *(uint32_t*)&t;
}
__device__ __forceinline__ void split4(float4 v, uint2& hi, uint2& lo) {
    float hx = __bfloat162float(__float2bfloat16(v.x));
    float hy = __bfloat162float(__float2bfloat16(v.y));
    float hz = __bfloat162float(__float2bfloat16(v.z));
    float hw = __bfloat162float(__float2bfloat16(v.w));
    hi = make_uint2(bf2(hx, hy), bf2(hz, hw));
    lo = make_uint2(bf2(v.x - hx, v.y - hy), bf2(v.z - hz, v.w - hw));
}
__global__ __launch_bounds__(256)
void prep_kernel(const float4* __restrict__ X4, const float4* __restrict__ Wc4) {
    int t = blockIdx.x * 256 + threadIdx.x;
    if (t < NIMG * C / 4) {
        uint2 hi, lo;
        split4(X4[t], hi, lo);
        ((uint2*)g_Xhi)[t] = hi;
        ((uint2*)g_Xlo)[t] = lo;
    }
    if (t < C * C / 4) {
        int o = t / (C / 4);
        int k = (t % (C / 4)) * 4;
        // Wc[(o*C+k)*2 + tap]: two float4s cover k..k+3, taps interleaved
        float4 w0 = Wc4[(o * C + k) / 2];
        float4 w1 = Wc4[(o * C + k) / 2 + 1];
        float4 t0 = make_float4(w0.x, w0.z, w1.x, w1.z);   // tap 0
        float4 t1 = make_float4(w0.y, w0.w, w1.y, w1.w);   // tap 1
        uint2 hi, lo;
        int i0 = (o * C + k) / 4;              // row o       (tap0 section)
        int i1 = (C * C + o * C + k) / 4;      // row C+o     (tap1 section)
        split4(t0, hi, lo);
        ((uint2*)g_Bhi)[i0] = hi; ((uint2*)g_Blo)[i0] = lo;
        split4(t1, hi, lo);
        ((uint2*)g_Bhi)[i1] = hi; ((uint2*)g_Blo)[i1] = lo;
    }
}

// ---------------- bf16 mma.sync GEMM + fused Threefry mask gen ----------------
// Y[8192,2560] = Xsplit @ Bsplit^T  (3 planes folded into K), and g_n1[] filled.
__global__ __launch_bounds__(256)
void gemm_mma_kernel() {
    extern __shared__ char dsm[];
    const uint32_t sbase = smem_u32(dsm);

    const int tid  = threadIdx.x;
    const int lane = tid & 31;
    const int wrp  = tid >> 5;
    const int wm   = wrp & 1;        // 2 warps along M (64 rows each)
    const int wn   = wrp >> 1;       // 4 warps along N (64 cols each)
    const int bm   = blockIdx.y * TMt;
    const int bn   = blockIdx.x * TNt;
    const uint32_t gtid =
        (uint32_t)(blockIdx.y * gridDim.x + blockIdx.x) * 256u + (uint32_t)tid;

    // Lane-invariant swizzled ldmatrix offsets. swz flips bits 4-6 from bits
    // 7-9; the mt/g*1024 additions only touch bits >=10 (safe to add), but the
    // ks*32 term (bit 5) must be XORed.
    const int rowA  = wm * 64 + ((lane >> 3) & 1) * 8 + (lane & 7);
    const int unitA = (lane >> 4) & 1;
    const uint32_t aOff = swz((uint32_t)(rowA * 64 + unitA * 16));
    const int rowB  = wn * 64 + ((lane >> 4) & 1) * 8 + (lane & 7);
    const int unitB = (lane >> 3) & 1;
    const uint32_t bOff = 8192u + swz((uint32_t)(rowB * 64 + unitB * 16));

    float acc[4][8][4];
#pragma unroll
    for (int i = 0; i < 4; i++)
#pragma unroll
        for (int j = 0; j < 8; j++)
#pragma unroll
            for (int k = 0; k < 4; k++) acc[i][j][k] = 0.f;

    const __nv_bfloat16* Apl[3] = {g_Xhi, g_Xhi, g_Xlo};
    const __nv_bfloat16* Bpl[3] = {g_Bhi, g_Blo, g_Bhi};

    auto load_chunk = [&](int kidx, int stage) {
        const int plane = kidx / 40;
        const int k0 = (kidx % 40) * KCH;
        const __nv_bfloat16* Ap = Apl[plane];
        const __nv_bfloat16* Bp = Bpl[plane];
        const uint32_t aB = sbase + stage * STAGE_BYTES;
        const uint32_t bB = aB + 8192;
#pragma unroll
        for (int i = 0; i < 2; i++) {          // A: 128 rows x 4 units = 512
            int idx = tid + i * 256;
            int row = idx >> 2, u = idx & 3;
            cp16(aB + swz((uint32_t)(row * 64 + u * 16)),
                 Ap + (size_t)(bm + row) * C + k0 + u * 8);
        }
#pragma unroll
        for (int i = 0; i < 4; i++) {          // B: 256 rows x 4 units = 1024
            int idx = tid + i * 256;
            int row = idx >> 2, u = idx & 3;
            cp16(bB + swz((uint32_t)(row * 64 + u * 16)),
                 Bp + (size_t)(bn + row) * C + k0 + u * 8);
        }
        CP_COMMIT();
    };

    // prologue: stages 0..2
    load_chunk(0, 0); load_chunk(1, 1); load_chunk(2, 2);

#pragma unroll 1
    for (int i = 0; i < NCHUNK; i++) {
        asm volatile("cp.async.wait_group 2;" ::: "memory");
        __syncthreads();

        if (i + 3 < NCHUNK) load_chunk(i + 3, (i + 3) & 3);
        else CP_COMMIT();   // keep group count uniform

        // fused dropout-mask generation: fills alu slots while warps wait on
        // L2/cp.async. f = i*TOT_THREADS + gtid is warp-coalesced.
        if (i < MASK_ITERS) {
            uint32_t f = (uint32_t)i * TOT_THREADS + gtid;
            g_n1[f] = (uint8_t)tf_n1(f);
        }

        const uint32_t stA = sbase + (i & 3) * STAGE_BYTES;
#pragma unroll
        for (int ks = 0; ks < 2; ks++) {
            uint32_t aF[4][4], bF[4][4];
#pragma unroll
            for (int mt = 0; mt < 4; mt++)
                ldm_x4(aF[mt], ((stA + aOff + mt * 1024) ^ (ks * 32)));
#pragma unroll
            for (int g = 0; g < 4; g++)
                ldm_x4(bF[g], ((stA + bOff + g * 1024) ^ (ks * 32)));
#pragma unroll
            for (int mt = 0; mt < 4; mt++)
#pragma unroll
                for (int nt = 0; nt < 8; nt++)
                    mma_bf16(acc[mt][nt], aF[mt], bF[nt >> 1][(nt & 1) * 2],
                             bF[nt >> 1][(nt & 1) * 2 + 1]);
        }
    }

    // epilogue: direct fp32 stores (float2 per fragment row)
    const bool plane1 = (bn >= C);
    float* Yp = plane1 ? g_Y1 : g_Y0;
    const int bn_loc = plane1 ? (bn - C) : bn;
    const int r0 = bm + wm * 64 + (lane >> 2);
    const int cbase = bn_loc + wn * 64 + (lane & 3) * 2;
#pragma unroll
    for (int mt = 0; mt < 4; mt++) {
#pragma unroll
        for (int nt = 0; nt < 8; nt++) {
            const int col = cbase + nt * 8;
            *(float2*)&Yp[(size_t)(r0 + mt * 16) * C + col] =
                make_float2(acc[mt][nt][0], acc[mt][nt][1]);
            *(float2*)&Yp[(size_t)(r0 + mt * 16 + 8) * C + col] =
                make_float2(acc[mt][nt][2], acc[mt][nt][3]);
        }
    }
}

// ---------------- Kernel B: relu + n1 lookup + 3 heads + segment mean ----
__global__ __launch_bounds__(256, 4)
void reduce_kernel(const float* __restrict__ bc,
                   const float* __restrict__ W0, const float* __restrict__ b0,
                   const float* __restrict__ W1, const float* __restrict__ b1,
                   const float* __restrict__ W2, const float* __restrict__ b2,
                   float* __restrict__ out) {
    __shared__ float sW0[C], sW1[C], sW2[C], sbc[C];
    __shared__ float red[24];

    const int tid = threadIdx.x;
    for (int i = tid; i < C; i += 256) {
        sW0[i] = W0[i]; sW1[i] = W1[i]; sW2[i] = W2[i]; sbc[i] = bc[i];
    }
    __syncthreads();

    const int b = blockIdx.x;

    float a0 = 0.f, a1 = 0.f, a2 = 0.f;

#pragma unroll
    for (int j = 0; j < PAIRS; j++) {
        const int ii = (j < 3) ? 0 : ((j < 5) ? 1 : 2);
        const int jj = (j < 3) ? (j + 1) : ((j < 5) ? (j - 1) : 3);
        const float* y0 = g_Y0 + (size_t)(4 * b + ii) * C;
        const float* y1 = g_Y1 + (size_t)(4 * b + jj) * C;
        const uint8_t* n1p = g_n1 + (size_t)(PAIRS * b + j) * C;

        for (int c = tid; c < C; c += 256) {
            float xc = fmaxf(y0[c] + y1[c] + sbc[c], 0.f);
            float t = xc * (float)(int)n1p[c];
            a0 = fmaf(t, sW0[c], a0);
            a1 = fmaf(t, sW1[c], a1);
            a2 = fmaf(t, sW2[c], a2);
        }
    }

    float vals[3] = {a0, a1, a2};
    const int lane = tid & 31, wid = tid >> 5;
#pragma unroll
    for (int v = 0; v < 3; v++) {
        float s = vals[v];
#pragma unroll
        for (int off = 16; off; off >>= 1) s += __shfl_down_sync(0xffffffffu, s, off);
        if (lane == 0) red[v * 8 + wid] = s;
    }
    __syncthreads();
    if (tid < 3) {
        float s = 0.f;
#pragma unroll
        for (int w = 0; w < 8; w++) s += red[tid * 8 + w];
        const float* bias = (tid == 0) ? b0 : ((tid == 1) ? b1 : b2);
        out[b * 3 + tid] = bias[0] + s * (1.0f / 15.0f);
    }
}

extern "C" void kernel_launch(void* const* d_in, const int* in_sizes, int n_in,
                              void* d_out, int out_size) {
    (void)in_sizes; (void)n_in; (void)out_size;
    const float* x  = (const float*)d_in[0];
    // d_in[1] = ids2 (static structure) — unused
    const float* Wc = (const float*)d_in[2];
    const float* bc = (const float*)d_in[3];
    const float* W0 = (const float*)d_in[4];
    const float* b0 = (const float*)d_in[5];
    const float* W1 = (const float*)d_in[6];
    const float* b1 = (const float*)d_in[7];
    const float* W2 = (const float*)d_in[8];
    const float* b2 = (const float*)d_in[9];
    float* out = (float*)d_out;

    cudaFuncSetAttribute(gemm_mma_kernel, cudaFuncAttributeMaxDynamicSharedMemorySize,
                         DYN_SMEM);

    prep_kernel<<<(NIMG * C / 4 + 255) / 256, 256>>>((const float4*)x, (const float4*)Wc);
    dim3 gridG(2 * C / TNt, NIMG / TMt);   // (10, 64) = 640 CTAs
    gemm_mma_kernel<<<gridG, 256, DYN_SMEM>>>();
    reduce_kernel<<<NPAT, 256>>>(bc, W0, b0, W1, b1, W2, b2, out);
}

// round 16
// speedup vs baseline: 1.2456x; 1.2456x over previous
#include <cuda_runtime.h>
#include <cuda_bf16.h>
#include <stdint.h>

#define C 1280
#define NIMG 8192          // B*K = 2048*4
#define NPAT 2048
#define PAIRS 6
#define PC 15728640u       // 12288 * 1280  (mask plane stride per dropout)

// ---- GEMM tiling: CTA 128x128, 8 warps (2 M x 4 N), warp 64x32 ----
#define TMt 128
#define TNt 128
#define KCH 32             // bf16 K elems per chunk = 64 B/row
#define NCHUNK 120         // 3 planes * (1280/32)
#define NSTAGE 4
#define STAGE_BYTES 16384  // A 8KB + B 8KB
#define DYN_SMEM (NSTAGE * STAGE_BYTES)
#define MASK_ITERS 48      // 48 * 327680 threads == PAIRS*NPAT*C elements
#define TOT_THREADS 327680u

// Scratch — 256B-aligned: cp.async needs 16B, vector stores need 8B.
__device__ __align__(256) float g_Y0[NIMG * C];
__device__ __align__(256) float g_Y1[NIMG * C];
__device__ __align__(256) __nv_bfloat16 g_Xhi[NIMG * C];
__device__ __align__(256) __nv_bfloat16 g_Xlo[NIMG * C];
__device__ __align__(256) __nv_bfloat16 g_Bhi[2 * C * C];  // 0..1279: tap0, 1280..2559: tap1
__device__ __align__(256) __nv_bfloat16 g_Blo[2 * C * C];
__device__ __align__(256) uint8_t g_n1[PAIRS * NPAT * C];  // keep-count per (pair, c)

// ---------------- helpers ----------------
__device__ __forceinline__ uint32_t smem_u32(const void* p) {
    uint32_t a;
    asm("{ .reg .u64 t; cvta.to.shared.u64 t, %1; cvt.u32.u64 %0, t; }" : "=r"(a) : "l"(p));
    return a;
}
// 64B rows, swizzle XORs (row/2)&7 into the 16B-unit bits -> conflict-free ldmatrix
__device__ __forceinline__ uint32_t swz(uint32_t o) { return o ^ (((o >> 7) & 7u) << 4); }

__device__ __forceinline__ void cp16(uint32_t dst, const void* src) {
    asm volatile("cp.async.cg.shared.global [%0], [%1], 16;" :: "r"(dst), "l"(src) : "memory");
}
#define CP_COMMIT() asm volatile("cp.async.commit_group;" ::: "memory")

__device__ __forceinline__ void ldm_x4(uint32_t* r, uint32_t addr) {
    asm volatile("ldmatrix.sync.aligned.m8n8.x4.shared.b16 {%0,%1,%2,%3}, [%4];"
                 : "=r"(r[0]), "=r"(r[1]), "=r"(r[2]), "=r"(r[3]) : "r"(addr));
}
__device__ __forceinline__ void mma_bf16(float* c, const uint32_t* a, uint32_t b0, uint32_t b1) {
    asm volatile(
        "mma.sync.aligned.m16n8k16.row.col.f32.bf16.bf16.f32 "
        "{%0,%1,%2,%3}, {%4,%5,%6,%7}, {%8,%9}, {%0,%1,%2,%3};"
        : "+f"(c[0]), "+f"(c[1]), "+f"(c[2]), "+f"(c[3])
        : "r"(a[0]), "r"(a[1]), "r"(a[2]), "r"(a[3]), "r"(b0), "r"(b1));
}

// ---------------- Threefry-2x32, JAX partitionable stream ----------------
__device__ __forceinline__ uint32_t rotl32(uint32_t x, int r) {
    return __funnelshift_l(x, x, r);
}
__device__ __forceinline__ int tf_n1(uint32_t base) {
    const uint32_t ks0 = 0u, ks1 = 42u, ks2 = 0x1BD11BF0u;
    uint32_t x0[5], x1[5];
#pragma unroll
    for (int d = 0; d < 5; d++) {
        x0[d] = ks0;
        x1[d] = base + (uint32_t)d * PC + ks1;
    }
#define TF_ROUND(r)                                           \
    {                                                         \
        _Pragma("unroll") for (int e = 0; e < 5; e++) {       \
            x0[e] += x1[e];                                   \
            x1[e] = rotl32(x1[e], (r));                       \
            x1[e] ^= x0[e];                                   \
        }                                                     \
    }
#define TF_INJ(a, b)                                          \
    {                                                         \
        _Pragma("unroll") for (int e = 0; e < 5; e++) {       \
            x0[e] += (a); x1[e] += (b);                       \
        }                                                     \
    }
    TF_ROUND(13) TF_ROUND(15) TF_ROUND(26) TF_ROUND(6)  TF_INJ(ks1, ks2 + 1u)
    TF_ROUND(17) TF_ROUND(29) TF_ROUND(16) TF_ROUND(24) TF_INJ(ks2, ks0 + 2u)
    TF_ROUND(13) TF_ROUND(15) TF_ROUND(26) TF_ROUND(6)  TF_INJ(ks0, ks1 + 3u)
    TF_ROUND(17) TF_ROUND(29) TF_ROUND(16) TF_ROUND(24) TF_INJ(ks1, ks2 + 4u)
    TF_ROUND(13) TF_ROUND(15) TF_ROUND(26) TF_ROUND(6)  TF_INJ(ks2, ks0 + 5u)
#undef TF_ROUND
#undef TF_INJ
    int msum = 0;
#pragma unroll
    for (int d = 0; d < 5; d++) msum += (int)((x0[d] ^ x1[d]) >> 31);
    return 5 - msum;
}

// ---------------- prep: split fp32 -> bf16 hi/lo (vectorized x4) ----------------
__device__ __forceinline__ uint32_t bf2(float a, float b) {
    __nv_bfloat162 t = __floats2bfloat162_rn(a, b);
    return *(uint32_t*)&t;
}
__device__ __forceinline__ void split4(float4 v, uint2& hi, uint2& lo) {
    float hx = __bfloat162float(__float2bfloat16(v.x));
    float hy = __bfloat162float(__float2bfloat16(v.y));
    float hz = __bfloat162float(__float2bfloat16(v.z));
    float hw = __bfloat162float(__float2bfloat16(v.w));
    hi = make_uint2(bf2(hx, hy), bf2(hz, hw));
    lo = make_uint2(bf2(v.x - hx, v.y - hy), bf2(v.z - hz, v.w - hw));
}
__global__ __launch_bounds__(256)
void prep_kernel(const float4* __restrict__ X4, const float4* __restrict__ Wc4) {
    int t = blockIdx.x * 256 + threadIdx.x;
    if (t < NIMG * C / 4) {
        uint2 hi, lo;
        split4(X4[t], hi, lo);
        ((uint2*)g_Xhi)[t] = hi;
        ((uint2*)g_Xlo)[t] = lo;
    }
    if (t < C * C / 4) {
        int o = t / (C / 4);
        int k = (t % (C / 4)) * 4;
        // Wc[(o*C+k)*2 + tap]: two float4s cover k..k+3, taps interleaved
        float4 w0 = Wc4[(o * C + k) / 2];
        float4 w1 = Wc4[(o * C + k) / 2 + 1];
        float4 t0 = make_float4(w0.x, w0.z, w1.x, w1.z);   // tap 0
        float4 t1 = make_float4(w0.y, w0.w, w1.y, w1.w);   // tap 1
        uint2 hi, lo;
        int i0 = (o * C + k) / 4;              // row o       (tap0 section)
        int i1 = (C * C + o * C + k) / 4;      // row C+o     (tap1 section)
        split4(t0, hi, lo);
        ((uint2*)g_Bhi)[i0] = hi; ((uint2*)g_Blo)[i0] = lo;
        split4(t1, hi, lo);
        ((uint2*)g_Bhi)[i1] = hi; ((uint2*)g_Blo)[i1] = lo;
    }
}

// ---------------- bf16 mma.sync GEMM (128x128) + fused Threefry mask gen ----
// Y[8192,2560] = Xsplit @ Bsplit^T  (3 planes folded into K), and g_n1[] filled.
__global__ __launch_bounds__(256, 2)
void gemm_mma_kernel() {
    extern __shared__ char dsm[];
    const uint32_t sbase = smem_u32(dsm);

    const int tid  = threadIdx.x;
    const int lane = tid & 31;
    const int wrp  = tid >> 5;
    const int wm   = wrp & 1;        // 2 warps along M
    const int wn   = wrp >> 1;       // 4 warps along N
    const int bm   = blockIdx.y * TMt;
    const int bn   = blockIdx.x * TNt;
    const uint32_t gtid =
        (uint32_t)(blockIdx.y * gridDim.x + blockIdx.x) * 256u + (uint32_t)tid;

    // Lane-invariant swizzled ldmatrix offsets. swz flips bits 4-6 from bits
    // 7-9; mt/p*1024 additions only touch bits >=10 (safe to add), but the
    // ks*32 term (bit 5) must be XORed.
    const int rowA  = wm * 64 + ((lane >> 3) & 1) * 8 + (lane & 7);
    const int unitA = (lane >> 4) & 1;
    const uint32_t aOff = swz((uint32_t)(rowA * 64 + unitA * 16));
    const int rowB  = wn * 32 + ((lane >> 4) & 1) * 8 + (lane & 7);
    const int unitB = (lane >> 3) & 1;
    const uint32_t bOff = 8192u + swz((uint32_t)(rowB * 64 + unitB * 16));

    float acc[4][4][4];
#pragma unroll
    for (int i = 0; i < 4; i++)
#pragma unroll
        for (int j = 0; j < 4; j++)
#pragma unroll
            for (int k = 0; k < 4; k++) acc[i][j][k] = 0.f;

    const __nv_bfloat16* Apl[3] = {g_Xhi, g_Xhi, g_Xlo};
    const __nv_bfloat16* Bpl[3] = {g_Bhi, g_Blo, g_Bhi};

    auto load_chunk = [&](int kidx, int stage) {
        const int plane = kidx / 40;
        const int k0 = (kidx % 40) * KCH;
        const __nv_bfloat16* Ap = Apl[plane];
        const __nv_bfloat16* Bp = Bpl[plane];
        const uint32_t aB = sbase + stage * STAGE_BYTES;
        const uint32_t bB = aB + 8192;
#pragma unroll
        for (int i = 0; i < 2; i++) {
            int idx = tid + i * 256;
            int row = idx >> 2, u = idx & 3;
            cp16(aB + swz((uint32_t)(row * 64 + u * 16)),
                 Ap + (size_t)(bm + row) * C + k0 + u * 8);
        }
#pragma unroll
        for (int i = 0; i < 2; i++) {
            int idx = tid + i * 256;
            int row = idx >> 2, u = idx & 3;
            cp16(bB + swz((uint32_t)(row * 64 + u * 16)),
                 Bp + (size_t)(bn + row) * C + k0 + u * 8);
        }
        CP_COMMIT();
    };

    // prologue: stages 0..2
    load_chunk(0, 0); load_chunk(1, 1); load_chunk(2, 2);

#pragma unroll 1
    for (int i = 0; i < NCHUNK; i++) {
        asm volatile("cp.async.wait_group 2;" ::: "memory");
        __syncthreads();

        if (i + 3 < NCHUNK) load_chunk(i + 3, (i + 3) & 3);
        else CP_COMMIT();   // keep group count uniform

        // fused dropout-mask generation: alu-pipe work that hides in the
        // GEMM's idle issue slots. f = i*TOT_THREADS + gtid is warp-coalesced.
        if (i < MASK_ITERS) {
            uint32_t f = (uint32_t)i * TOT_THREADS + gtid;
            g_n1[f] = (uint8_t)tf_n1(f);
        }

        const uint32_t stA = sbase + (i & 3) * STAGE_BYTES;
#pragma unroll
        for (int ks = 0; ks < 2; ks++) {
            uint32_t aF[4][4], bF[2][4];
#pragma unroll
            for (int mt = 0; mt < 4; mt++)
                ldm_x4(aF[mt], ((stA + aOff + mt * 1024) ^ (ks * 32)));
#pragma unroll
            for (int p = 0; p < 2; p++)
                ldm_x4(bF[p], ((stA + bOff + p * 1024) ^ (ks * 32)));
#pragma unroll
            for (int mt = 0; mt < 4; mt++)
#pragma unroll
                for (int nt = 0; nt < 4; nt++)
                    mma_bf16(acc[mt][nt], aF[mt], bF[nt >> 1][(nt & 1) * 2],
                             bF[nt >> 1][(nt & 1) * 2 + 1]);
        }
    }

    // epilogue: direct fp32 stores (float2 per fragment row)
    const bool plane1 = (bn >= C);
    float* Yp = plane1 ? g_Y1 : g_Y0;
    const int bn_loc = plane1 ? (bn - C) : bn;
    const int r0 = bm + wm * 64 + (lane >> 2);
    const int cbase = bn_loc + wn * 32 + (lane & 3) * 2;
#pragma unroll
    for (int mt = 0; mt < 4; mt++) {
#pragma unroll
        for (int nt = 0; nt < 4; nt++) {
            const int col = cbase + nt * 8;
            *(float2*)&Yp[(size_t)(r0 + mt * 16) * C + col] =
                make_float2(acc[mt][nt][0], acc[mt][nt][1]);
            *(float2*)&Yp[(size_t)(r0 + mt * 16 + 8) * C + col] =
                make_float2(acc[mt][nt][2], acc[mt][nt][3]);
        }
    }
}

// ---------------- Kernel B: relu + n1 lookup + 3 heads + segment mean ----
__global__ __launch_bounds__(256, 4)
void reduce_kernel(const float* __restrict__ bc,
                   const float* __restrict__ W0, const float* __restrict__ b0,
                   const float* __restrict__ W1, const float* __restrict__ b1,
                   const float* __restrict__ W2, const float* __restrict__ b2,
                   float* __restrict__ out) {
    __shared__ float sW0[C], sW1[C], sW2[C], sbc[C];
    __shared__ float red[24];

    const int tid = threadIdx.x;
    for (int i = tid; i < C; i += 256) {
        sW0[i] = W0[i]; sW1[i] = W1[i]; sW2[i] = W2[i]; sbc[i] = bc[i];
    }
    __syncthreads();

    const int b = blockIdx.x;

    float a0 = 0.f, a1 = 0.f, a2 = 0.f;

#pragma unroll
    for (int j = 0; j < PAIRS; j++) {
        const int ii = (j < 3) ? 0 : ((j < 5) ? 1 : 2);
        const int jj = (j < 3) ? (j + 1) : ((j < 5) ? (j - 1) : 3);
        const float* y0 = g_Y0 + (size_t)(4 * b + ii) * C;
        const float* y1 = g_Y1 + (size_t)(4 * b + jj) * C;
        const uint8_t* n1p = g_n1 + (size_t)(PAIRS * b + j) * C;

        for (int c = tid; c < C; c += 256) {
            float xc = fmaxf(y0[c] + y1[c] + sbc[c], 0.f);
            float t = xc * (float)(int)n1p[c];
            a0 = fmaf(t, sW0[c], a0);
            a1 = fmaf(t, sW1[c], a1);
            a2 = fmaf(t, sW2[c], a2);
        }
    }

    float vals[3] = {a0, a1, a2};
    const int lane = tid & 31, wid = tid >> 5;
#pragma unroll
    for (int v = 0; v < 3; v++) {
        float s = vals[v];
#pragma unroll
        for (int off = 16; off; off >>= 1) s += __shfl_down_sync(0xffffffffu, s, off);
        if (lane == 0) red[v * 8 + wid] = s;
    }
    __syncthreads();
    if (tid < 3) {
        float s = 0.f;
#pragma unroll
        for (int w = 0; w < 8; w++) s += red[tid * 8 + w];
        const float* bias = (tid == 0) ? b0 : ((tid == 1) ? b1 : b2);
        out[b * 3 + tid] = bias[0] + s * (1.0f / 15.0f);
    }
}

extern "C" void kernel_launch(void* const* d_in, const int* in_sizes, int n_in,
                              void* d_out, int out_size) {
    (void)in_sizes; (void)n_in; (void)out_size;
    const float* x  = (const float*)d_in[0];
    // d_in[1] = ids2 (static structure) — unused
    const float* Wc = (const float*)d_in[2];
    const float* bc = (const float*)d_in[3];
    const float* W0 = (const float*)d_in[4];
    const float* b0 = (const float*)d_in[5];
    const float* W1 = (const float*)d_in[6];
    const float* b1 = (const float*)d_in[7];
    const float* W2 = (const float*)d_in[8];
    const float* b2 = (const float*)d_in[9];
    float* out = (float*)d_out;

    cudaFuncSetAttribute(gemm_mma_kernel, cudaFuncAttributeMaxDynamicSharedMemorySize,
                         DYN_SMEM);

    prep_kernel<<<(NIMG * C / 4 + 255) / 256, 256>>>((const float4*)x, (const float4*)Wc);
    dim3 gridG(2 * C / TNt, NIMG / TMt);   // (20, 64) = 1280 CTAs
    gemm_mma_kernel<<<gridG, 256, DYN_SMEM>>>();
    reduce_kernel<<<NPAT, 256>>>(bc, W0, b0, W1, b1, W2, b2, out);
}

// round 17
// speedup vs baseline: 2.2432x; 1.8009x over previous
#include <cuda_runtime.h>
#include <cuda_fp16.h>
#include <stdint.h>

#define C 1280
#define NIMG 8192          // B*K = 2048*4
#define NPAT 2048
#define PAIRS 6
#define PC 15728640u       // 12288 * 1280  (mask plane stride per dropout)

// ---- GEMM tiling: CTA 128x128, 8 warps (2 M x 4 N), warp 64x32 ----
#define TMt 128
#define TNt 128
#define KCH 32             // fp16 K elems per chunk = 64 B/row
#define NCHUNK 40          // single fp16 plane: 1280/32
#define NSTAGE 4
#define STAGE_BYTES 16384  // A 8KB + B 8KB
#define DYN_SMEM (NSTAGE * STAGE_BYTES)

// Scratch — 256B-aligned: cp.async needs 16B, vector stores need 8B.
__device__ __align__(256) float g_Y0[NIMG * C];
__device__ __align__(256) float g_Y1[NIMG * C];
__device__ __align__(256) __half g_Xh[NIMG * C];
__device__ __align__(256) __half g_Bh[2 * C * C];  // 0..1279: tap0, 1280..2559: tap1

// ---------------- helpers ----------------
__device__ __forceinline__ uint32_t smem_u32(const void* p) {
    uint32_t a;
    asm("{ .reg .u64 t; cvta.to.shared.u64 t, %1; cvt.u32.u64 %0, t; }" : "=r"(a) : "l"(p));
    return a;
}
// 64B rows, swizzle XORs (row/2)&7 into the 16B-unit bits -> conflict-free ldmatrix
__device__ __forceinline__ uint32_t swz(uint32_t o) { return o ^ (((o >> 7) & 7u) << 4); }

__device__ __forceinline__ void cp16(uint32_t dst, const void* src) {
    asm volatile("cp.async.cg.shared.global [%0], [%1], 16;" :: "r"(dst), "l"(src) : "memory");
}
#define CP_COMMIT() asm volatile("cp.async.commit_group;" ::: "memory")

__device__ __forceinline__ void ldm_x4(uint32_t* r, uint32_t addr) {
    asm volatile("ldmatrix.sync.aligned.m8n8.x4.shared.b16 {%0,%1,%2,%3}, [%4];"
                 : "=r"(r[0]), "=r"(r[1]), "=r"(r[2]), "=r"(r[3]) : "r"(addr));
}
__device__ __forceinline__ void mma_fp16(float* c, const uint32_t* a, uint32_t b0, uint32_t b1) {
    asm volatile(
        "mma.sync.aligned.m16n8k16.row.col.f32.f16.f16.f32 "
        "{%0,%1,%2,%3}, {%4,%5,%6,%7}, {%8,%9}, {%0,%1,%2,%3};"
        : "+f"(c[0]), "+f"(c[1]), "+f"(c[2]), "+f"(c[3])
        : "r"(a[0]), "r"(a[1]), "r"(a[2]), "r"(a[3]), "r"(b0), "r"(b1));
}

// ---------------- prep: fp32 -> fp16 (vectorized x4) ----------------
__device__ __forceinline__ uint2 h4(float4 v) {
    __half2 lo = __floats2half2_rn(v.x, v.y);
    __half2 hi = __floats2half2_rn(v.z, v.w);
    return make_uint2(*(uint32_t*)&lo, *(uint32_t*)&hi);
}
__global__ __launch_bounds__(256)
void prep_kernel(const float4* __restrict__ X4, const float4* __restrict__ Wc4) {
    int t = blockIdx.x * 256 + threadIdx.x;
    if (t < NIMG * C / 4) {
        ((uint2*)g_Xh)[t] = h4(X4[t]);
    }
    if (t < C * C / 4) {
        int o = t / (C / 4);
        int k = (t % (C / 4)) * 4;
        // Wc[(o*C+k)*2 + tap]: two float4s cover k..k+3, taps interleaved
        float4 w0 = Wc4[(o * C + k) / 2];
        float4 w1 = Wc4[(o * C + k) / 2 + 1];
        float4 t0 = make_float4(w0.x, w0.z, w1.x, w1.z);   // tap 0
        float4 t1 = make_float4(w0.y, w0.w, w1.y, w1.w);   // tap 1
        ((uint2*)g_Bh)[(o * C + k) / 4]         = h4(t0);  // row o (tap0)
        ((uint2*)g_Bh)[(C * C + o * C + k) / 4] = h4(t1);  // row C+o (tap1)
    }
}

// ---------------- fp16 mma.sync GEMM (128x128): Y[8192,2560] = Xh @ Bh^T ----
__global__ __launch_bounds__(256, 2)
void gemm_mma_kernel() {
    extern __shared__ char dsm[];
    const uint32_t sbase = smem_u32(dsm);

    const int tid  = threadIdx.x;
    const int lane = tid & 31;
    const int wrp  = tid >> 5;
    const int wm   = wrp & 1;        // 2 warps along M
    const int wn   = wrp >> 1;       // 4 warps along N
    const int bm   = blockIdx.y * TMt;
    const int bn   = blockIdx.x * TNt;

    // Lane-invariant swizzled ldmatrix offsets. swz flips bits 4-6 from bits
    // 7-9; mt/p*1024 additions only touch bits >=10 (safe to add), but the
    // ks*32 term (bit 5) must be XORed.
    const int rowA  = wm * 64 + ((lane >> 3) & 1) * 8 + (lane & 7);
    const int unitA = (lane >> 4) & 1;
    const uint32_t aOff = swz((uint32_t)(rowA * 64 + unitA * 16));
    const int rowB  = wn * 32 + ((lane >> 4) & 1) * 8 + (lane & 7);
    const int unitB = (lane >> 3) & 1;
    const uint32_t bOff = 8192u + swz((uint32_t)(rowB * 64 + unitB * 16));

    float acc[4][4][4];
#pragma unroll
    for (int i = 0; i < 4; i++)
#pragma unroll
        for (int j = 0; j < 4; j++)
#pragma unroll
            for (int k = 0; k < 4; k++) acc[i][j][k] = 0.f;

    auto load_chunk = [&](int kidx, int stage) {
        const int k0 = kidx * KCH;
        const uint32_t aB = sbase + stage * STAGE_BYTES;
        const uint32_t bB = aB + 8192;
#pragma unroll
        for (int i = 0; i < 2; i++) {
            int idx = tid + i * 256;
            int row = idx >> 2, u = idx & 3;
            cp16(aB + swz((uint32_t)(row * 64 + u * 16)),
                 g_Xh + (size_t)(bm + row) * C + k0 + u * 8);
        }
#pragma unroll
        for (int i = 0; i < 2; i++) {
            int idx = tid + i * 256;
            int row = idx >> 2, u = idx & 3;
            cp16(bB + swz((uint32_t)(row * 64 + u * 16)),
                 g_Bh + (size_t)(bn + row) * C + k0 + u * 8);
        }
        CP_COMMIT();
    };

    // prologue: stages 0..2
    load_chunk(0, 0); load_chunk(1, 1); load_chunk(2, 2);

#pragma unroll 1
    for (int i = 0; i < NCHUNK; i++) {
        asm volatile("cp.async.wait_group 2;" ::: "memory");
        __syncthreads();

        if (i + 3 < NCHUNK) load_chunk(i + 3, (i + 3) & 3);
        else CP_COMMIT();   // keep group count uniform

        const uint32_t stA = sbase + (i & 3) * STAGE_BYTES;
#pragma unroll
        for (int ks = 0; ks < 2; ks++) {
            uint32_t aF[4][4], bF[2][4];
#pragma unroll
            for (int mt = 0; mt < 4; mt++)
                ldm_x4(aF[mt], ((stA + aOff + mt * 1024) ^ (ks * 32)));
#pragma unroll
            for (int p = 0; p < 2; p++)
                ldm_x4(bF[p], ((stA + bOff + p * 1024) ^ (ks * 32)));
#pragma unroll
            for (int mt = 0; mt < 4; mt++)
#pragma unroll
                for (int nt = 0; nt < 4; nt++)
                    mma_fp16(acc[mt][nt], aF[mt], bF[nt >> 1][(nt & 1) * 2],
                             bF[nt >> 1][(nt & 1) * 2 + 1]);
        }
    }

    // epilogue: direct fp32 stores (float2 per fragment row)
    const bool plane1 = (bn >= C);
    float* Yp = plane1 ? g_Y1 : g_Y0;
    const int bn_loc = plane1 ? (bn - C) : bn;
    const int r0 = bm + wm * 64 + (lane >> 2);
    const int cbase = bn_loc + wn * 32 + (lane & 3) * 2;
#pragma unroll
    for (int mt = 0; mt < 4; mt++) {
#pragma unroll
        for (int nt = 0; nt < 4; nt++) {
            const int col = cbase + nt * 8;
            *(float2*)&Yp[(size_t)(r0 + mt * 16) * C + col] =
                make_float2(acc[mt][nt][0], acc[mt][nt][1]);
            *(float2*)&Yp[(size_t)(r0 + mt * 16 + 8) * C + col] =
                make_float2(acc[mt][nt][2], acc[mt][nt][3]);
        }
    }
}

// ---------------- Threefry-2x32, JAX partitionable stream ----------------
__device__ __forceinline__ uint32_t rotl32(uint32_t x, int r) {
    return __funnelshift_l(x, x, r);
}
__device__ __forceinline__ int tf_n1(uint32_t base) {
    const uint32_t ks0 = 0u, ks1 = 42u, ks2 = 0x1BD11BF0u;
    uint32_t x0[5], x1[5];
#pragma unroll
    for (int d = 0; d < 5; d++) {
        x0[d] = ks0;
        x1[d] = base + (uint32_t)d * PC + ks1;
    }
#define TF_ROUND(r)                                           \
    {                                                         \
        _Pragma("unroll") for (int e = 0; e < 5; e++) {       \
            x0[e] += x1[e];                                   \
            x1[e] = rotl32(x1[e], (r));                       \
            x1[e] ^= x0[e];                                   \
        }                                                     \
    }
#define TF_INJ(a, b)                                          \
    {                                                         \
        _Pragma("unroll") for (int e = 0; e < 5; e++) {       \
            x0[e] += (a); x1[e] += (b);                       \
        }                                                     \
    }
    TF_ROUND(13) TF_ROUND(15) TF_ROUND(26) TF_ROUND(6)  TF_INJ(ks1, ks2 + 1u)
    TF_ROUND(17) TF_ROUND(29) TF_ROUND(16) TF_ROUND(24) TF_INJ(ks2, ks0 + 2u)
    TF_ROUND(13) TF_ROUND(15) TF_ROUND(26) TF_ROUND(6)  TF_INJ(ks0, ks1 + 3u)
    TF_ROUND(17) TF_ROUND(29) TF_ROUND(16) TF_ROUND(24) TF_INJ(ks1, ks2 + 4u)
    TF_ROUND(13) TF_ROUND(15) TF_ROUND(26) TF_ROUND(6)  TF_INJ(ks2, ks0 + 5u)
#undef TF_ROUND
#undef TF_INJ
    int msum = 0;
#pragma unroll
    for (int d = 0; d < 5; d++) msum += (int)((x0[d] ^ x1[d]) >> 31);
    return 5 - msum;
}

// ---------------- Kernel B: relu + inline Threefry + 3 heads + segment mean ----
__global__ __launch_bounds__(256, 4)
void reduce_kernel(const float* __restrict__ bc,
                   const float* __restrict__ W0, const float* __restrict__ b0,
                   const float* __restrict__ W1, const float* __restrict__ b1,
                   const float* __restrict__ W2, const float* __restrict__ b2,
                   float* __restrict__ out) {
    __shared__ float sW0[C], sW1[C], sW2[C], sbc[C];
    __shared__ float red[24];

    const int tid = threadIdx.x;
    for (int i = tid; i < C; i += 256) {
        sW0[i] = W0[i]; sW1[i] = W1[i]; sW2[i] = W2[i]; sbc[i] = bc[i];
    }
    __syncthreads();

    const int b = blockIdx.x;

    float a0 = 0.f, a1 = 0.f, a2 = 0.f;

#pragma unroll
    for (int j = 0; j < PAIRS; j++) {
        const int ii = (j < 3) ? 0 : ((j < 5) ? 1 : 2);
        const int jj = (j < 3) ? (j + 1) : ((j < 5) ? (j - 1) : 3);
        const float* y0 = g_Y0 + (size_t)(4 * b + ii) * C;
        const float* y1 = g_Y1 + (size_t)(4 * b + jj) * C;
        const uint32_t p = (uint32_t)(PAIRS * b + j);

        for (int c = tid; c < C; c += 256) {
            float xc = fmaxf(y0[c] + y1[c] + sbc[c], 0.f);
            const int n1 = tf_n1(p * 1280u + (uint32_t)c);
            float t = xc * (float)n1;
            a0 = fmaf(t, sW0[c], a0);
            a1 = fmaf(t, sW1[c], a1);
            a2 = fmaf(t, sW2[c], a2);
        }
    }

    float vals[3] = {a0, a1, a2};
    const int lane = tid & 31, wid = tid >> 5;
#pragma unroll
    for (int v = 0; v < 3; v++) {
        float s = vals[v];
#pragma unroll
        for (int off = 16; off; off >>= 1) s += __shfl_down_sync(0xffffffffu, s, off);
        if (lane == 0) red[v * 8 + wid] = s;
    }
    __syncthreads();
    if (tid < 3) {
        float s = 0.f;
#pragma unroll
        for (int w = 0; w < 8; w++) s += red[tid * 8 + w];
        const float* bias = (tid == 0) ? b0 : ((tid == 1) ? b1 : b2);
        out[b * 3 + tid] = bias[0] + s * (1.0f / 15.0f);
    }
}

extern "C" void kernel_launch(void* const* d_in, const int* in_sizes, int n_in,
                              void* d_out, int out_size) {
    (void)in_sizes; (void)n_in; (void)out_size;
    const float* x  = (const float*)d_in[0];
    // d_in[1] = ids2 (static structure) — unused
    const float* Wc = (const float*)d_in[2];
    const float* bc = (const float*)d_in[3];
    const float* W0 = (const float*)d_in[4];
    const float* b0 = (const float*)d_in[5];
    const float* W1 = (const float*)d_in[6];
    const float* b1 = (const float*)d_in[7];
    const float* W2 = (const float*)d_in[8];
    const float* b2 = (const float*)d_in[9];
    float* out = (float*)d_out;

    cudaFuncSetAttribute(gemm_mma_kernel, cudaFuncAttributeMaxDynamicSharedMemorySize,
                         DYN_SMEM);

    prep_kernel<<<(NIMG * C / 4 + 255) / 256, 256>>>((const float4*)x, (const float4*)Wc);
    dim3 gridG(2 * C / TNt, NIMG / TMt);   // (20, 64) = 1280 CTAs
    gemm_mma_kernel<<<gridG, 256, DYN_SMEM>>>();
    reduce_kernel<<<NPAT, 256>>>(bc, W0, b0, W1, b1, W2, b2, out);
}